// round 1
// baseline (speedup 1.0000x reference)
#include <cuda_runtime.h>
#include <math.h>

// Problem constants
#define Bb    8
#define Nn    1024
#define FIN   512
#define FOUT  256
#define Hh    8
#define ALPHAs 0.2f
#define BN    (Bb * Nn)      // 8192 rows (b,n)
#define HBN   (Hh * BN)      // 65536 rows (head,b,n)

// Scratch (device globals — no allocation allowed)
__device__ float g_h[(size_t)Hh * BN * FOUT];     // 64 MB: h per head
__device__ float g_head[(size_t)Hh * BN * FOUT];  // 64 MB: elu(head outputs)
__device__ float g_f1[HBN], g_f2[HBN];
__device__ float g_E1p[HBN], g_E1n[HBN];
__device__ float g_E2p[HBN], g_E2n[HBN];

// ---------------------------------------------------------------------------
// Kernel 1: h[head, row, o] = sum_f X[row, f] * W[head, o, f]
// Block tile: 64 rows x 256 cols (one full head), K-tile 16. 256 threads,
// each thread an 8x8 register tile (rows warp*8+i, cols lane*4+c / 128+lane*4+c).
// ---------------------------------------------------------------------------
__global__ __launch_bounds__(256, 2) void k_gemm_h(const float* __restrict__ X,
                                                   const float* __restrict__ W) {
    const int head = blockIdx.y;
    const int r0   = blockIdx.x * 64;
    const int tid  = threadIdx.x;
    const int warp = tid >> 5, lane = tid & 31;

    __shared__ float Xs[16][64];    // [k][row]
    __shared__ float Ws[16][FOUT];  // [k][o]

    float acc[8][8];
#pragma unroll
    for (int i = 0; i < 8; i++)
#pragma unroll
        for (int j = 0; j < 8; j++) acc[i][j] = 0.f;

    const float* Wh = W + (size_t)head * FOUT * FIN;
    const int lrow = tid >> 2;        // 0..63
    const int lf   = (tid & 3) * 4;   // 0,4,8,12
    const int wo   = tid;             // 0..255

    for (int k0 = 0; k0 < FIN; k0 += 16) {
        __syncthreads();
        // X tile: 64 x 16
        float4 xv = *(const float4*)(X + (size_t)(r0 + lrow) * FIN + k0 + lf);
        Xs[lf + 0][lrow] = xv.x; Xs[lf + 1][lrow] = xv.y;
        Xs[lf + 2][lrow] = xv.z; Xs[lf + 3][lrow] = xv.w;
        // W tile: 256 x 16 (transposed into Ws[k][o])
#pragma unroll
        for (int q = 0; q < 4; q++) {
            float4 wv = *(const float4*)(Wh + (size_t)wo * FIN + k0 + q * 4);
            Ws[q * 4 + 0][wo] = wv.x; Ws[q * 4 + 1][wo] = wv.y;
            Ws[q * 4 + 2][wo] = wv.z; Ws[q * 4 + 3][wo] = wv.w;
        }
        __syncthreads();
#pragma unroll
        for (int k = 0; k < 16; k++) {
            float xr[8];
#pragma unroll
            for (int i = 0; i < 8; i++) xr[i] = Xs[k][warp * 8 + i];
            float4 wa = *(const float4*)&Ws[k][lane * 4];
            float4 wb = *(const float4*)&Ws[k][128 + lane * 4];
#pragma unroll
            for (int i = 0; i < 8; i++) {
                acc[i][0] += xr[i] * wa.x; acc[i][1] += xr[i] * wa.y;
                acc[i][2] += xr[i] * wa.z; acc[i][3] += xr[i] * wa.w;
                acc[i][4] += xr[i] * wb.x; acc[i][5] += xr[i] * wb.y;
                acc[i][6] += xr[i] * wb.z; acc[i][7] += xr[i] * wb.w;
            }
        }
    }

#pragma unroll
    for (int i = 0; i < 8; i++) {
        const int row = r0 + warp * 8 + i;
        float* dst = g_h + ((size_t)head * BN + row) * FOUT;
#pragma unroll
        for (int c = 0; c < 4; c++) dst[lane * 4 + c]       = acc[i][c];
#pragma unroll
        for (int c = 0; c < 4; c++) dst[128 + lane * 4 + c] = acc[i][4 + c];
    }
}

// ---------------------------------------------------------------------------
// Kernel 2: f1/f2 dots + factored exps. One warp per (head,b,n) row.
// ---------------------------------------------------------------------------
__global__ void k_fvec(const float* __restrict__ a1, const float* __restrict__ a2) {
    const int row  = blockIdx.x * 8 + (threadIdx.x >> 5);  // 0..HBN-1
    const int lane = threadIdx.x & 31;
    const int head = row >> 13;  // row / 8192
    const float* hr = g_h + (size_t)row * FOUT;
    float s1 = 0.f, s2 = 0.f;
#pragma unroll
    for (int q = 0; q < 2; q++) {
        float4 hv  = *(const float4*)(hr + lane * 8 + q * 4);
        float4 av1 = *(const float4*)(a1 + head * FOUT + lane * 8 + q * 4);
        float4 av2 = *(const float4*)(a2 + head * FOUT + lane * 8 + q * 4);
        s1 += hv.x * av1.x + hv.y * av1.y + hv.z * av1.z + hv.w * av1.w;
        s2 += hv.x * av2.x + hv.y * av2.y + hv.z * av2.z + hv.w * av2.w;
    }
#pragma unroll
    for (int off = 16; off; off >>= 1) {
        s1 += __shfl_xor_sync(0xffffffffu, s1, off);
        s2 += __shfl_xor_sync(0xffffffffu, s2, off);
    }
    if (lane == 0) {
        g_f1[row]  = s1;
        g_f2[row]  = s2;
        g_E1p[row] = expf(s1);
        g_E1n[row] = expf(ALPHAs * s1);
        g_E2p[row] = expf(s2);
        g_E2n[row] = expf(ALPHAs * s2);
    }
}

// ---------------------------------------------------------------------------
// Kernel 3: fused masked-softmax attention as a GEMM with on-the-fly P.
//   P_ij = adj ? ((f1_i+f2_j>=0) ? E1p_i*E2p_j : E1n_i*E2n_j) : 0
//   out_i = elu( (sum_j P_ij h_j) / (sum_j P_ij) )   -> g_head
// Block: one (head,b), 64 rows x all 256 cols, j-tiles of 16. 256 threads.
// ---------------------------------------------------------------------------
__global__ __launch_bounds__(256, 2) void k_attn(const int* __restrict__ adj) {
    const int head = blockIdx.z;
    const int b    = blockIdx.y;
    const int i0   = blockIdx.x * 64;
    const int tid  = threadIdx.x, warp = tid >> 5, lane = tid & 31;
    const int rowbase = head * BN + b * Nn;  // index into f-arrays / g_h rows

    __shared__ float Vs[16][256];  // [jj][c]
    __shared__ float Ps[64][16];   // [i][jj]
    __shared__ float f1s[64], E1ps[64], E1ns[64];

    if (tid < 64) {
        f1s[tid]  = g_f1[rowbase + i0 + tid];
        E1ps[tid] = g_E1p[rowbase + i0 + tid];
        E1ns[tid] = g_E1n[rowbase + i0 + tid];
    }

    float acc[8][8];
#pragma unroll
    for (int i = 0; i < 8; i++)
#pragma unroll
        for (int j = 0; j < 8; j++) acc[i][j] = 0.f;
    float rsum[8];
#pragma unroll
    for (int i = 0; i < 8; i++) rsum[i] = 0.f;

    const float* V    = g_h + (size_t)rowbase * FOUT;
    const int*   adjb = adj + (size_t)b * Nn * Nn;

    const int vc  = (tid & 63) * 4;  // V loader: col 0..252
    const int vj0 = tid >> 6;        // V loader: jj base 0..3
    const int pi  = tid >> 2;        // P-gen: row 0..63
    const int ps  = (tid & 3) * 4;   // P-gen: jj 0,4,8,12

    for (int j0 = 0; j0 < Nn; j0 += 16) {
        __syncthreads();
        // Stage V tile (16 x 256), coalesced float4
#pragma unroll
        for (int q = 0; q < 4; q++) {
            const int jj = vj0 + q * 4;
            *(float4*)&Vs[jj][vc] = *(const float4*)(V + (size_t)(j0 + jj) * FOUT + vc);
        }
        // Generate P tile (64 x 16)
        {
            int4 av = *(const int4*)(adjb + (size_t)(i0 + pi) * Nn + j0 + ps);
            const float f1v = f1s[pi], e1p = E1ps[pi], e1n = E1ns[pi];
            const int ja = rowbase + j0 + ps;
            float4 pv;
            pv.x = av.x ? ((f1v + g_f2[ja + 0] >= 0.f) ? e1p * g_E2p[ja + 0]
                                                       : e1n * g_E2n[ja + 0]) : 0.f;
            pv.y = av.y ? ((f1v + g_f2[ja + 1] >= 0.f) ? e1p * g_E2p[ja + 1]
                                                       : e1n * g_E2n[ja + 1]) : 0.f;
            pv.z = av.z ? ((f1v + g_f2[ja + 2] >= 0.f) ? e1p * g_E2p[ja + 2]
                                                       : e1n * g_E2n[ja + 2]) : 0.f;
            pv.w = av.w ? ((f1v + g_f2[ja + 3] >= 0.f) ? e1p * g_E2p[ja + 3]
                                                       : e1n * g_E2n[ja + 3]) : 0.f;
            *(float4*)&Ps[pi][ps] = pv;
        }
        __syncthreads();
        // Accumulate: acc += P_tile @ V_tile; rsum += row sums of P
#pragma unroll
        for (int k = 0; k < 16; k++) {
            float p[8];
#pragma unroll
            for (int i = 0; i < 8; i++) {
                p[i] = Ps[warp * 8 + i][k];
                rsum[i] += p[i];
            }
            float4 va = *(const float4*)&Vs[k][lane * 4];
            float4 vb = *(const float4*)&Vs[k][128 + lane * 4];
#pragma unroll
            for (int i = 0; i < 8; i++) {
                acc[i][0] += p[i] * va.x; acc[i][1] += p[i] * va.y;
                acc[i][2] += p[i] * va.z; acc[i][3] += p[i] * va.w;
                acc[i][4] += p[i] * vb.x; acc[i][5] += p[i] * vb.y;
                acc[i][6] += p[i] * vb.z; acc[i][7] += p[i] * vb.w;
            }
        }
    }

    // Epilogue: normalize, elu, store per-head output
    float* O = g_head + (size_t)rowbase * FOUT;
#pragma unroll
    for (int i = 0; i < 8; i++) {
        const float inv = 1.0f / rsum[i];
        const int r = i0 + warp * 8 + i;
#pragma unroll
        for (int c = 0; c < 8; c++) {
            const int col = (c < 4) ? (lane * 4 + c) : (128 + lane * 4 + (c - 4));
            float v = acc[i][c] * inv;
            v = (v > 0.f) ? v : (expf(v) - 1.f);
            O[(size_t)r * FOUT + col] = v;
        }
    }
}

// ---------------------------------------------------------------------------
// Kernel 4: out[b,n,:] = log_softmax( sum_h g_head[h,b,n,:] )
// One block per (b,n) row, 256 threads (one per feature).
// ---------------------------------------------------------------------------
__global__ void k_final(float* __restrict__ out) {
    const int row  = blockIdx.x;   // 0..BN-1
    const int o    = threadIdx.x;  // 0..255
    const int lane = o & 31, warp = o >> 5;

    float s = 0.f;
#pragma unroll
    for (int h = 0; h < Hh; h++)
        s += g_head[((size_t)h * BN + row) * FOUT + o];

    __shared__ float red[8];
    // max reduce
    float m = s;
#pragma unroll
    for (int off = 16; off; off >>= 1)
        m = fmaxf(m, __shfl_xor_sync(0xffffffffu, m, off));
    if (lane == 0) red[warp] = m;
    __syncthreads();
    float mm = red[0];
#pragma unroll
    for (int w = 1; w < 8; w++) mm = fmaxf(mm, red[w]);
    __syncthreads();
    // sum exp reduce
    float e = expf(s - mm);
#pragma unroll
    for (int off = 16; off; off >>= 1)
        e += __shfl_xor_sync(0xffffffffu, e, off);
    if (lane == 0) red[warp] = e;
    __syncthreads();
    float tot = 0.f;
#pragma unroll
    for (int w = 0; w < 8; w++) tot += red[w];

    out[(size_t)row * FOUT + o] = s - mm - logf(tot);
}

// ---------------------------------------------------------------------------
extern "C" void kernel_launch(void* const* d_in, const int* in_sizes, int n_in,
                              void* d_out, int out_size) {
    const float* x   = (const float*)d_in[0];  // (B,N,FIN)
    const int*   adj = (const int*)d_in[1];    // (B,N,N)
    const float* W   = (const float*)d_in[2];  // (H,FOUT,FIN)
    const float* a1  = (const float*)d_in[3];  // (H,FOUT)
    const float* a2  = (const float*)d_in[4];  // (H,FOUT)
    float* out = (float*)d_out;                // (B,N,FOUT)

    k_gemm_h<<<dim3(BN / 64, Hh), 256>>>(x, W);
    k_fvec<<<HBN / 8, 256>>>(a1, a2);
    k_attn<<<dim3(Nn / 64, Bb, Hh), 256>>>(adj);
    k_final<<<BN, 256>>>(out);
}